// round 1
// baseline (speedup 1.0000x reference)
#include <cuda_runtime.h>
#include <math_constants.h>

// Problem constants
#define H_HEADS 16
#define NB 2
#define L_SEQ 4096
#define E_DIM 1024
#define D_HEAD 64
#define NH (NB * H_HEADS)   // 32 (n,h) pairs
#define PAD 68              // smem row pad (floats): keeps float4 alignment, kills bank conflicts

// Scratch (no allocations allowed -> __device__ globals)
__device__ float g_qp[(size_t)NH * L_SEQ * D_HEAD];   // [N,H,L,D]
__device__ float g_kp[(size_t)NH * L_SEQ * D_HEAD];
__device__ float g_vp[(size_t)NH * L_SEQ * D_HEAD];
__device__ float g_attn[(size_t)NB * L_SEQ * E_DIM];  // attention output, [N,L,E]

// ---------------------------------------------------------------------------
// Kernel 1: per-head projections. out[n,h,l,o] = sum_d X[n,l,h*64+d] * W[o,d]
// grid: (L/32, NH, 3), block 256
// ---------------------------------------------------------------------------
__global__ __launch_bounds__(256) void proj_kernel(
    const float* __restrict__ Xq, const float* __restrict__ Xk, const float* __restrict__ Xv,
    const float* __restrict__ Wq, const float* __restrict__ Wk, const float* __restrict__ Wv)
{
    __shared__ float Wt[64][PAD];   // Wt[d][o] = W[o][d]
    __shared__ float Xs[32][PAD];

    const float* X; const float* W; float* O;
    if (blockIdx.z == 0)      { X = Xq; W = Wq; O = g_qp; }
    else if (blockIdx.z == 1) { X = Xk; W = Wk; O = g_kp; }
    else                      { X = Xv; W = Wv; O = g_vp; }

    const int nh = blockIdx.y;
    const int n = nh / H_HEADS, h = nh % H_HEADS;
    const int l0 = blockIdx.x * 32;
    const int tid = threadIdx.x;

    for (int i = tid; i < 64 * 64; i += 256) {
        Wt[i & 63][i >> 6] = W[i];                       // W[o*64+d] -> Wt[d][o]
    }
    for (int i = tid; i < 32 * 64; i += 256) {
        int r = i >> 6, d = i & 63;
        Xs[r][d] = X[((size_t)(n * L_SEQ + l0 + r)) * E_DIM + h * D_HEAD + d];
    }
    __syncthreads();

    const int r  = tid >> 3;          // 0..31
    const int o0 = (tid & 7) << 3;    // 0,8,...,56

    float acc[8] = {0.f,0.f,0.f,0.f,0.f,0.f,0.f,0.f};
    #pragma unroll 8
    for (int d = 0; d < 64; d++) {
        float xv = Xs[r][d];
        float4 w0 = *(float4*)&Wt[d][o0];
        float4 w1 = *(float4*)&Wt[d][o0 + 4];
        acc[0] = fmaf(xv, w0.x, acc[0]);
        acc[1] = fmaf(xv, w0.y, acc[1]);
        acc[2] = fmaf(xv, w0.z, acc[2]);
        acc[3] = fmaf(xv, w0.w, acc[3]);
        acc[4] = fmaf(xv, w1.x, acc[4]);
        acc[5] = fmaf(xv, w1.y, acc[5]);
        acc[6] = fmaf(xv, w1.z, acc[6]);
        acc[7] = fmaf(xv, w1.w, acc[7]);
    }
    size_t base = ((size_t)nh * L_SEQ + l0 + r) * D_HEAD + o0;
    *(float4*)&O[base]     = make_float4(acc[0], acc[1], acc[2], acc[3]);
    *(float4*)&O[base + 4] = make_float4(acc[4], acc[5], acc[6], acc[7]);
}

// ---------------------------------------------------------------------------
// Kernel 2: flash attention, fp32. One block = one (n,h) head x 64 queries.
// 256 threads as 16(tq) x 16(tk); each thread owns a 4x4 tile of S and of O.
// grid: (L/64, NH), block 256, dynamic smem 4*64*PAD floats
// ---------------------------------------------------------------------------
__global__ __launch_bounds__(256) void attn_kernel()
{
    extern __shared__ float sm[];
    float* Qs = sm;                 // [d][q]  (d-major, transposed)
    float* Ks = sm + 64 * PAD;      // [d][k]
    float* Vs = sm + 2 * 64 * PAD;  // [j][d]
    float* Ps = sm + 3 * 64 * PAD;  // [q][j]

    const int nh = blockIdx.y;
    const int q0 = blockIdx.x * 64;
    const float* Qh = g_qp + (size_t)nh * L_SEQ * D_HEAD;
    const float* Kh = g_kp + (size_t)nh * L_SEQ * D_HEAD;
    const float* Vh = g_vp + (size_t)nh * L_SEQ * D_HEAD;

    const int tid = threadIdx.x;
    const int tq = tid >> 4;   // 0..15 -> query rows tq*4..tq*4+3
    const int tk = tid & 15;   // 0..15 -> key cols / d cols tk*4..tk*4+3

    // Load Q tile transposed: Qs[d][q]
    for (int i = tid; i < 64 * 64; i += 256) {
        int rr = i >> 6, d = i & 63;
        Qs[d * PAD + rr] = Qh[(size_t)(q0 + rr) * D_HEAD + d];
    }

    float o[4][4];
    float m[4], lsum[4];
    #pragma unroll
    for (int a = 0; a < 4; a++) {
        m[a] = -CUDART_INF_F; lsum[a] = 0.f;
        #pragma unroll
        for (int b = 0; b < 4; b++) o[a][b] = 0.f;
    }

    for (int kb = 0; kb < L_SEQ / 64; kb++) {
        __syncthreads();  // previous PV done with Ps/Vs; Q ready on first iter
        const size_t kbase = (size_t)kb * 64 * D_HEAD;
        for (int i = tid; i < 64 * 64; i += 256) {
            int rr = i >> 6, d = i & 63;
            float kv = Kh[kbase + (size_t)rr * D_HEAD + d];
            float vv = Vh[kbase + (size_t)rr * D_HEAD + d];
            Ks[d * PAD + rr] = kv;   // transposed
            Vs[rr * PAD + d] = vv;   // row-major
        }
        __syncthreads();

        // S = Q K^T  (4x4 per thread)
        float s[4][4];
        #pragma unroll
        for (int a = 0; a < 4; a++)
            #pragma unroll
            for (int b = 0; b < 4; b++) s[a][b] = 0.f;

        #pragma unroll 8
        for (int d = 0; d < 64; d++) {
            float4 a = *(float4*)&Qs[d * PAD + tq * 4];
            float4 b = *(float4*)&Ks[d * PAD + tk * 4];
            s[0][0] = fmaf(a.x, b.x, s[0][0]); s[0][1] = fmaf(a.x, b.y, s[0][1]);
            s[0][2] = fmaf(a.x, b.z, s[0][2]); s[0][3] = fmaf(a.x, b.w, s[0][3]);
            s[1][0] = fmaf(a.y, b.x, s[1][0]); s[1][1] = fmaf(a.y, b.y, s[1][1]);
            s[1][2] = fmaf(a.y, b.z, s[1][2]); s[1][3] = fmaf(a.y, b.w, s[1][3]);
            s[2][0] = fmaf(a.z, b.x, s[2][0]); s[2][1] = fmaf(a.z, b.y, s[2][1]);
            s[2][2] = fmaf(a.z, b.z, s[2][2]); s[2][3] = fmaf(a.z, b.w, s[2][3]);
            s[3][0] = fmaf(a.w, b.x, s[3][0]); s[3][1] = fmaf(a.w, b.y, s[3][1]);
            s[3][2] = fmaf(a.w, b.z, s[3][2]); s[3][3] = fmaf(a.w, b.w, s[3][3]);
        }

        // online softmax; scale = 1/sqrt(E) = 1/32
        const float scale = 0.03125f;
        #pragma unroll
        for (int rr = 0; rr < 4; rr++) {
            float s0 = s[rr][0] * scale, s1 = s[rr][1] * scale;
            float s2 = s[rr][2] * scale, s3 = s[rr][3] * scale;
            float mx = fmaxf(fmaxf(s0, s1), fmaxf(s2, s3));
            // row max across the 16 threads sharing this tq (lanes 0-15 / 16-31)
            mx = fmaxf(mx, __shfl_xor_sync(0xffffffffu, mx, 1));
            mx = fmaxf(mx, __shfl_xor_sync(0xffffffffu, mx, 2));
            mx = fmaxf(mx, __shfl_xor_sync(0xffffffffu, mx, 4));
            mx = fmaxf(mx, __shfl_xor_sync(0xffffffffu, mx, 8));
            float mnew = fmaxf(m[rr], mx);
            float corr = __expf(m[rr] - mnew);  // exp(-inf)=0 on first iter
            m[rr] = mnew;
            float p0 = __expf(s0 - mnew), p1 = __expf(s1 - mnew);
            float p2 = __expf(s2 - mnew), p3 = __expf(s3 - mnew);
            lsum[rr] = lsum[rr] * corr + (p0 + p1 + p2 + p3);
            o[rr][0] *= corr; o[rr][1] *= corr; o[rr][2] *= corr; o[rr][3] *= corr;
            *(float4*)&Ps[(tq * 4 + rr) * PAD + tk * 4] = make_float4(p0, p1, p2, p3);
        }
        __syncthreads();

        // O += P V   (thread: rows tq*4.., d-cols tk*4..)
        #pragma unroll 2
        for (int j0 = 0; j0 < 64; j0 += 4) {
            float4 pr0 = *(float4*)&Ps[(tq * 4 + 0) * PAD + j0];
            float4 pr1 = *(float4*)&Ps[(tq * 4 + 1) * PAD + j0];
            float4 pr2 = *(float4*)&Ps[(tq * 4 + 2) * PAD + j0];
            float4 pr3 = *(float4*)&Ps[(tq * 4 + 3) * PAD + j0];
            #pragma unroll
            for (int jj = 0; jj < 4; jj++) {
                float4 v = *(float4*)&Vs[(j0 + jj) * PAD + tk * 4];
                float p0 = (jj == 0) ? pr0.x : (jj == 1) ? pr0.y : (jj == 2) ? pr0.z : pr0.w;
                float p1 = (jj == 0) ? pr1.x : (jj == 1) ? pr1.y : (jj == 2) ? pr1.z : pr1.w;
                float p2 = (jj == 0) ? pr2.x : (jj == 1) ? pr2.y : (jj == 2) ? pr2.z : pr2.w;
                float p3 = (jj == 0) ? pr3.x : (jj == 1) ? pr3.y : (jj == 2) ? pr3.z : pr3.w;
                o[0][0] = fmaf(p0, v.x, o[0][0]); o[0][1] = fmaf(p0, v.y, o[0][1]);
                o[0][2] = fmaf(p0, v.z, o[0][2]); o[0][3] = fmaf(p0, v.w, o[0][3]);
                o[1][0] = fmaf(p1, v.x, o[1][0]); o[1][1] = fmaf(p1, v.y, o[1][1]);
                o[1][2] = fmaf(p1, v.z, o[1][2]); o[1][3] = fmaf(p1, v.w, o[1][3]);
                o[2][0] = fmaf(p2, v.x, o[2][0]); o[2][1] = fmaf(p2, v.y, o[2][1]);
                o[2][2] = fmaf(p2, v.z, o[2][2]); o[2][3] = fmaf(p2, v.w, o[2][3]);
                o[3][0] = fmaf(p3, v.x, o[3][0]); o[3][1] = fmaf(p3, v.y, o[3][1]);
                o[3][2] = fmaf(p3, v.z, o[3][2]); o[3][3] = fmaf(p3, v.w, o[3][3]);
            }
        }
    }

    // finalize: reduce partial row sums across the 16-lane group, normalize
    const int n = nh / H_HEADS, h = nh % H_HEADS;
    #pragma unroll
    for (int rr = 0; rr < 4; rr++) {
        float t = lsum[rr];
        t += __shfl_xor_sync(0xffffffffu, t, 1);
        t += __shfl_xor_sync(0xffffffffu, t, 2);
        t += __shfl_xor_sync(0xffffffffu, t, 4);
        t += __shfl_xor_sync(0xffffffffu, t, 8);
        float inv = __fdividef(1.f, t);
        size_t idx = ((size_t)(n * L_SEQ) + q0 + tq * 4 + rr) * E_DIM + h * D_HEAD + tk * 4;
        *(float4*)&g_attn[idx] = make_float4(o[rr][0] * inv, o[rr][1] * inv,
                                             o[rr][2] * inv, o[rr][3] * inv);
    }
}

// ---------------------------------------------------------------------------
// Kernel 3: Y = attn @ Wfc^T + bfc.  [8192,1024] x [1024,1024]
// grid: (8192/64, 1024/64), block 256, 4x4 micro-tiles
// ---------------------------------------------------------------------------
__global__ __launch_bounds__(256) void fc_kernel(const float* __restrict__ Wfc,
                                                 const float* __restrict__ bfc,
                                                 float* __restrict__ Y)
{
    __shared__ float As[64][PAD];   // As[k][r]
    __shared__ float Ws[64][PAD];   // Ws[k][o]
    const int r0 = blockIdx.x * 64, o0 = blockIdx.y * 64;
    const int tid = threadIdx.x;
    const int tr = tid >> 4, tc = tid & 15;

    float acc[4][4];
    #pragma unroll
    for (int a = 0; a < 4; a++)
        #pragma unroll
        for (int b = 0; b < 4; b++) acc[a][b] = 0.f;

    for (int kt = 0; kt < E_DIM; kt += 64) {
        __syncthreads();
        for (int i = tid; i < 64 * 64; i += 256) {
            int rr = i >> 6, kk = i & 63;
            As[kk][rr] = g_attn[(size_t)(r0 + rr) * E_DIM + kt + kk];
            Ws[kk][rr] = Wfc[(size_t)(o0 + rr) * E_DIM + kt + kk];
        }
        __syncthreads();
        #pragma unroll 8
        for (int kk = 0; kk < 64; kk++) {
            float4 a = *(float4*)&As[kk][tr * 4];
            float4 b = *(float4*)&Ws[kk][tc * 4];
            acc[0][0] = fmaf(a.x, b.x, acc[0][0]); acc[0][1] = fmaf(a.x, b.y, acc[0][1]);
            acc[0][2] = fmaf(a.x, b.z, acc[0][2]); acc[0][3] = fmaf(a.x, b.w, acc[0][3]);
            acc[1][0] = fmaf(a.y, b.x, acc[1][0]); acc[1][1] = fmaf(a.y, b.y, acc[1][1]);
            acc[1][2] = fmaf(a.y, b.z, acc[1][2]); acc[1][3] = fmaf(a.y, b.w, acc[1][3]);
            acc[2][0] = fmaf(a.z, b.x, acc[2][0]); acc[2][1] = fmaf(a.z, b.y, acc[2][1]);
            acc[2][2] = fmaf(a.z, b.z, acc[2][2]); acc[2][3] = fmaf(a.z, b.w, acc[2][3]);
            acc[3][0] = fmaf(a.w, b.x, acc[3][0]); acc[3][1] = fmaf(a.w, b.y, acc[3][1]);
            acc[3][2] = fmaf(a.w, b.z, acc[3][2]); acc[3][3] = fmaf(a.w, b.w, acc[3][3]);
        }
    }

    const float4 bv = *(const float4*)&bfc[o0 + tc * 4];
    #pragma unroll
    for (int rr = 0; rr < 4; rr++) {
        float4 res = make_float4(acc[rr][0] + bv.x, acc[rr][1] + bv.y,
                                 acc[rr][2] + bv.z, acc[rr][3] + bv.w);
        *(float4*)&Y[(size_t)(r0 + tr * 4 + rr) * E_DIM + o0 + tc * 4] = res;
    }
}

// ---------------------------------------------------------------------------
extern "C" void kernel_launch(void* const* d_in, const int* in_sizes, int n_in,
                              void* d_out, int out_size)
{
    (void)in_sizes; (void)n_in; (void)out_size;
    const float* values  = (const float*)d_in[0];
    const float* keys    = (const float*)d_in[1];
    const float* queries = (const float*)d_in[2];
    const float* Wv  = (const float*)d_in[3];
    const float* Wk  = (const float*)d_in[4];
    const float* Wq  = (const float*)d_in[5];
    const float* Wfc = (const float*)d_in[6];
    const float* bfc = (const float*)d_in[7];
    float* out = (float*)d_out;

    const int attn_smem = 4 * 64 * PAD * (int)sizeof(float);  // 69632 B
    cudaFuncSetAttribute(attn_kernel, cudaFuncAttributeMaxDynamicSharedMemorySize, attn_smem);

    proj_kernel<<<dim3(L_SEQ / 32, NH, 3), 256>>>(queries, keys, values, Wq, Wk, Wv);
    attn_kernel<<<dim3(L_SEQ / 64, NH), 256, attn_smem>>>();
    fc_kernel<<<dim3(NB * L_SEQ / 64, E_DIM / 64), 256>>>(Wfc, bfc, out);
}